// round 10
// baseline (speedup 1.0000x reference)
#include <cuda_runtime.h>
#include <cuda_bf16.h>

#define T_MAX   16384
#define WIDTH   1024
#define GRID    128
#define THREADS 256
#define NW      8
#define CHUNK   8          // output dims per CTA per layer
#define WS      16
#define ALPHA   21
#define POLL_BUDGET (1u << 17)

typedef unsigned long long u64;

// ---- global scratch (static __device__ arrays: allocation-free) ----
// Pair format: high 32 bits = epoch, low 32 bits = f32 value bits.
__device__ __align__(16) int g_flags0[GRID];        // precompute barrier (R2-style)
__device__ int g_abort;
__device__ __align__(16) u64 g_h1p[WIDTH];          // h1 pairs
__device__ __align__(16) u64 g_h2p[WIDTH];          // h2 pairs
__device__ __align__(16) u64 g_pp[2 * GRID];        // partial pairs, parity-slotted
__device__ float g_hpre[(size_t)T_MAX * WIDTH];     // one-hot part of layer0, per timestep

__global__ void init_kernel() {
    int i = blockIdx.x * blockDim.x + threadIdx.x;
    if (i < WIDTH)    { g_h1p[i] = 0ull; g_h2p[i] = 0ull; }
    if (i < 2 * GRID) g_pp[i] = 0ull;
    if (i < GRID)     g_flags0[i] = 0;
    if (i == 0)       g_abort = 0;
}

// ------------------------------- helpers ----------------------------------
__device__ __forceinline__ void st_pair(u64* p, float v, unsigned e) {
    u64 x = ((u64)e << 32) | (u64)__float_as_uint(v);
    asm volatile("st.relaxed.gpu.global.u64 [%0], %1;" :: "l"(p), "l"(x) : "memory");
}
__device__ __forceinline__ int ld_abort() {
    int a;
    asm volatile("ld.global.cg.u32 %0, [%1];" : "=r"(a) : "l"(&g_abort) : "memory");
    return a;
}
__device__ __forceinline__ void set_abort() {
    asm volatile("st.global.cg.u32 [%0], %1;" :: "l"(&g_abort), "r"(1) : "memory");
}
__device__ __forceinline__ float4 ldcg4(const float4* p) {
    float4 v;
    asm volatile("ld.global.cg.v4.f32 {%0,%1,%2,%3}, [%4];"
                 : "=f"(v.x), "=f"(v.y), "=f"(v.z), "=f"(v.w) : "l"(p) : "memory");
    return v;
}

// Per-thread: poll 4 consecutive pairs (32B, two v2.u64 loads) until all epochs
// >= need; return the 4 values. Bounded by watchdog; zeros after abort.
__device__ __forceinline__ float4 poll4(const u64* base, unsigned need, int& dead) {
    if (dead) return make_float4(0.f, 0.f, 0.f, 0.f);
    unsigned cnt = 0;
    for (;;) {
        u64 a, b, c, d;
        asm volatile("ld.global.cg.v2.u64 {%0,%1}, [%2];"
                     : "=l"(a), "=l"(b) : "l"(base) : "memory");
        asm volatile("ld.global.cg.v2.u64 {%0,%1}, [%2];"
                     : "=l"(c), "=l"(d) : "l"(base + 2) : "memory");
        if ((unsigned)(a >> 32) >= need && (unsigned)(b >> 32) >= need &&
            (unsigned)(c >> 32) >= need && (unsigned)(d >> 32) >= need)
            return make_float4(__uint_as_float((unsigned)a), __uint_as_float((unsigned)b),
                               __uint_as_float((unsigned)c), __uint_as_float((unsigned)d));
        if ((++cnt & 255u) == 0u) {
            if (ld_abort()) { dead = 1; break; }
            if (cnt > POLL_BUDGET) { set_abort(); dead = 1; break; }
        }
        __nanosleep(40);
    }
    return make_float4(0.f, 0.f, 0.f, 0.f);
}

// R2-style bounded flag wait (used once, for the precompute barrier).
__device__ __forceinline__ void flagwait0(int lane) {
    const int4* fp = reinterpret_cast<const int4*>(g_flags0);
    unsigned cnt = 0;
    for (;;) {
        int4 v; int ab;
        asm volatile("ld.global.cg.v4.u32 {%0,%1,%2,%3}, [%4];"
                     : "=r"(v.x), "=r"(v.y), "=r"(v.z), "=r"(v.w)
                     : "l"(fp + lane) : "memory");
        asm volatile("ld.global.cg.u32 %0, [%1];"
                     : "=r"(ab) : "l"(&g_abort) : "memory");
        bool done = (v.x >= 1 && v.y >= 1 && v.z >= 1 && v.w >= 1) || (ab != 0);
        if (__all_sync(0xffffffffu, done)) break;
        if (++cnt > POLL_BUDGET) {
            if (lane == 0) set_abort();
            break;
        }
        __nanosleep(150);
    }
    __threadfence();
}

// One warp computes one dot(w_row[1024], h[1024]) from shared memory. (R2 verbatim)
__device__ __forceinline__ float gemv_warp(const float* __restrict__ wrow,
                                           const float* __restrict__ hbuf, int lane) {
    const float4* w4 = reinterpret_cast<const float4*>(wrow);
    const float4* h4 = reinterpret_cast<const float4*>(hbuf);
    float acc = 0.0f;
    #pragma unroll
    for (int i = 0; i < 8; i++) {
        float4 a = w4[i * 32 + lane];
        float4 b = h4[i * 32 + lane];
        acc += a.x * b.x + a.y * b.y + a.z * b.z + a.w * b.w;
    }
    #pragma unroll
    for (int d = 16; d > 0; d >>= 1) acc += __shfl_xor_sync(0xffffffffu, acc, d);
    return acc;
}

__global__ void __launch_bounds__(THREADS, 1)
seqff_kernel(const int* __restrict__ x,
             const float* __restrict__ W0,
             const float* __restrict__ b0,
             const float* __restrict__ Wh,
             const float* __restrict__ bh,
             const float* __restrict__ Wo,
             const float* __restrict__ bo,
             float* __restrict__ out,
             int T)
{
    extern __shared__ float smem[];
    float* Wys   = smem;                       // 16*1024: y-window rows of W0 (rows 357..372)
    float* Whs   = Wys + WS * WIDTH;           // 3*8*1024: this CTA's hidden-layer slices
    float* hbuf1 = Whs + 3 * CHUNK * WIDTH;    // 1024: staged h1
    float* hbuf2 = hbuf1 + WIDTH;              // 1024: staged h2
    float* h0s   = hbuf2 + WIDTH;              // 1024: locally computed h0
    float* ring  = h0s + WIDTH;                // 16: y history window
    float* out8  = ring + 16;                  // 8: layer-3 chunk outputs

    const int tid  = threadIdx.x;
    const int lane = tid & 31;
    const int w    = tid >> 5;
    const int bid  = blockIdx.x;
    const int o0   = bid * CHUNK;

    // ===================== load weights into SMEM (once) =====================
    for (int idx = tid; idx < WS * WIDTH; idx += THREADS)
        Wys[idx] = W0[(357 + (idx >> 10)) * WIDTH + (idx & (WIDTH - 1))];
    for (int l = 0; l < 3; l++)
        for (int idx = tid; idx < CHUNK * WIDTH; idx += THREADS) {
            int ww = idx & 7, j = idx >> 3;
            Whs[(l * CHUNK + ww) * WIDTH + j] = Wh[(size_t)l * WIDTH * WIDTH + (size_t)j * WIDTH + o0 + ww];
        }
    if (tid < 16) ring[tid] = -10.0f;

    const float bo_reg = __ldg(bo);
    const float bh0 = __ldg(bh + 0 * WIDTH + o0 + w);
    const float bh1 = __ldg(bh + 1 * WIDTH + o0 + w);
    const float bh2 = __ldg(bh + 2 * WIDTH + o0 + w);
    float wo[CHUNK];
    #pragma unroll
    for (int i = 0; i < CHUNK; i++) wo[i] = __ldg(Wo + o0 + i);
    __syncthreads();

    // =============== precompute one-hot part of layer 0 for all t ===============
    for (int t = bid; t < T; t += GRID) {
        float4 acc = reinterpret_cast<const float4*>(b0)[tid];
        if (t >= WS) {
            #pragma unroll
            for (int p = 0; p < WS + 1; p++) {
                int r = p * ALPHA + __ldg(x + t - WS + p);
                float4 wv = reinterpret_cast<const float4*>(W0 + (size_t)r * WIDTH)[tid];
                acc.x += wv.x; acc.y += wv.y; acc.z += wv.z; acc.w += wv.w;
            }
        } else {
            for (int p = 0; p < WS + 1; p++) {
                int pos = t - WS + p;
                if (pos >= 0) {
                    int r = p * ALPHA + __ldg(x + pos);
                    float4 wv = reinterpret_cast<const float4*>(W0 + (size_t)r * WIDTH)[tid];
                    acc.x += wv.x; acc.y += wv.y; acc.z += wv.z; acc.w += wv.w;
                } else {
                    for (int a = 0; a < ALPHA; a++) {
                        int r = p * ALPHA + a;
                        float4 wv = reinterpret_cast<const float4*>(W0 + (size_t)r * WIDTH)[tid];
                        acc.x += wv.x; acc.y += wv.y; acc.z += wv.z; acc.w += wv.w;
                    }
                }
            }
        }
        reinterpret_cast<float4*>(g_hpre + (size_t)t * WIDTH)[tid] = acc;
    }
    __syncthreads();
    if (tid == 0) {
        __threadfence();
        asm volatile("st.global.cg.u32 [%0], %1;" :: "l"(g_flags0 + bid), "r"(1) : "memory");
    }
    if (w == 0) flagwait0(lane);
    __syncthreads();

    // prefetch hpre row 0
    float4 hpre_reg = ldcg4(reinterpret_cast<const float4*>(g_hpre) + tid);

    int dead = 0;

    // ============================ sequential main loop ============================
    for (int t = 0; t < T; t++) {
        // ---- phase 1: y_{t-1} from partial pairs (every warp, redundantly) ----
        if (t > 0) {
            float4 pv = poll4(g_pp + ((t - 1) & 1) * GRID + 4 * lane, (unsigned)t, dead);
            float s = pv.x + pv.y + pv.z + pv.w;
            #pragma unroll
            for (int d = 16; d > 0; d >>= 1) s += __shfl_xor_sync(0xffffffffu, s, d);
            float y = fmaxf(s + bo_reg, 0.0f);
            if (bid == 0 && tid == 0) out[t - 1] = y;
            if (lane == 0) ring[(t + 15) & 15] = y;   // same value from all warps: benign
            __syncwarp();
        }
        // full h0 computed locally by every CTA
        {
            float4 h = hpre_reg;
            #pragma unroll
            for (int k = 0; k < WS; k++) {
                float yk = ring[(t + k) & 15];
                float4 wy = reinterpret_cast<const float4*>(Wys + k * WIDTH)[tid];
                h.x += yk * wy.x; h.y += yk * wy.y; h.z += yk * wy.z; h.w += yk * wy.w;
            }
            h.x = fmaxf(h.x, 0.0f); h.y = fmaxf(h.y, 0.0f);
            h.z = fmaxf(h.z, 0.0f); h.w = fmaxf(h.w, 0.0f);
            reinterpret_cast<float4*>(h0s)[tid] = h;
        }
        __syncthreads();                       // BAR-D: h0s ready

        // ---- phase 1b: layer-1 GEMV; per-warp IMMEDIATE publish of its dim ----
        {
            float v = gemv_warp(Whs + (0 * CHUNK + w) * WIDTH, h0s, lane);
            v = fmaxf(v + bh0, 0.0f);
            if (lane == 0) st_pair(&g_h1p[o0 + w], v, (unsigned)(t + 1));
        }
        // prefetch next step's hpre row (hidden behind hops 2 and 3)
        if (t + 1 < T)
            hpre_reg = ldcg4(reinterpret_cast<const float4*>(g_hpre + (size_t)(t + 1) * WIDTH) + tid);

        // ---- phase 2: poll h1 pairs (this thread's 4 dims) into hbuf1 ----
        {
            float4 hv = poll4(g_h1p + 4 * tid, (unsigned)(t + 1), dead);
            reinterpret_cast<float4*>(hbuf1)[tid] = hv;
        }
        __syncthreads();                       // BAR-A: hbuf1 staged
        {
            float v = gemv_warp(Whs + (1 * CHUNK + w) * WIDTH, hbuf1, lane);
            v = fmaxf(v + bh1, 0.0f);
            if (lane == 0) st_pair(&g_h2p[o0 + w], v, (unsigned)(t + 1));
        }

        // ---- phase 3: poll h2 pairs into hbuf2 ----
        {
            float4 hv = poll4(g_h2p + 4 * tid, (unsigned)(t + 1), dead);
            reinterpret_cast<float4*>(hbuf2)[tid] = hv;
        }
        __syncthreads();                       // BAR-B: hbuf2 staged
        {
            float v = gemv_warp(Whs + (2 * CHUNK + w) * WIDTH, hbuf2, lane);
            v = fmaxf(v + bh2, 0.0f);
            if (lane == 0) out8[w] = v;
        }
        __syncthreads();                       // BAR-C: out8 ready
        if (tid == 0) {
            float p = 0.0f;
            #pragma unroll
            for (int i = 0; i < CHUNK; i++) p += out8[i] * wo[i];
            st_pair(&g_pp[(t & 1) * GRID + bid], p, (unsigned)(t + 1));
        }
    }

    // ---------------- epilogue: final output y[T-1] ----------------
    if (bid == 0 && w == 0) {
        float4 pv = poll4(g_pp + ((T - 1) & 1) * GRID + 4 * lane, (unsigned)T, dead);
        float s = pv.x + pv.y + pv.z + pv.w;
        #pragma unroll
        for (int d = 16; d > 0; d >>= 1) s += __shfl_xor_sync(0xffffffffu, s, d);
        if (lane == 0) out[T - 1] = fmaxf(s + bo_reg, 0.0f);
    }
}

extern "C" void kernel_launch(void* const* d_in, const int* in_sizes, int n_in,
                              void* d_out, int out_size)
{
    const int*   x  = (const int*)  d_in[0];
    const float* W0 = (const float*)d_in[1];
    const float* b0 = (const float*)d_in[2];
    const float* Wh = (const float*)d_in[3];
    const float* bh = (const float*)d_in[4];
    const float* Wo = (const float*)d_in[5];
    const float* bo = (const float*)d_in[6];
    float* out = (float*)d_out;
    int T = in_sizes[0];
    if (T > T_MAX) T = T_MAX;

    const int smem_bytes = (WS * WIDTH + 3 * CHUNK * WIDTH + 3 * WIDTH + 16 + 8) * 4;
    cudaFuncSetAttribute(seqff_kernel, cudaFuncAttributeMaxDynamicSharedMemorySize, smem_bytes);

    init_kernel<<<4, 512>>>();
    seqff_kernel<<<GRID, THREADS, smem_bytes>>>(x, W0, b0, Wh, bh, Wo, bo, out, T);
}

// round 11
// speedup vs baseline: 1.9753x; 1.9753x over previous
#include <cuda_runtime.h>
#include <cuda_bf16.h>

#define T_MAX   16384
#define WIDTH   1024
#define GRID    64
#define THREADS 512
#define NW      16
#define CHUNK   16         // output dims per CTA per layer
#define WS      16
#define ALPHA   21
#define POLL_BUDGET (1u << 17)

typedef unsigned long long u64;

// ---- global scratch (static __device__ arrays: allocation-free) ----
// Pair format: high 32 bits = epoch, low 32 bits = f32 value bits.
__device__ __align__(16) int g_flags0[GRID];        // precompute barrier
__device__ int g_abort;
__device__ __align__(16) u64 g_h1p[WIDTH];          // h1 pairs
__device__ __align__(16) u64 g_h2p[WIDTH];          // h2 pairs
__device__ __align__(16) u64 g_pp[2 * GRID];        // partial pairs, parity-slotted
__device__ float g_hpre[(size_t)T_MAX * WIDTH];     // one-hot part of layer0, per timestep

__global__ void init_kernel() {
    int i = blockIdx.x * blockDim.x + threadIdx.x;
    if (i < WIDTH)    { g_h1p[i] = 0ull; g_h2p[i] = 0ull; }
    if (i < 2 * GRID) g_pp[i] = 0ull;
    if (i < GRID)     g_flags0[i] = 0;
    if (i == 0)       g_abort = 0;
}

// ------------------------------- helpers ----------------------------------
__device__ __forceinline__ void st_pair(u64* p, float v, unsigned e) {
    u64 x = ((u64)e << 32) | (u64)__float_as_uint(v);
    asm volatile("st.relaxed.gpu.global.u64 [%0], %1;" :: "l"(p), "l"(x) : "memory");
}
__device__ __forceinline__ int ld_abort() {
    int a;
    asm volatile("ld.global.cg.u32 %0, [%1];" : "=r"(a) : "l"(&g_abort) : "memory");
    return a;
}
__device__ __forceinline__ void set_abort() {
    asm volatile("st.global.cg.u32 [%0], %1;" :: "l"(&g_abort), "r"(1) : "memory");
}

// Per-thread: poll 2 consecutive pairs (one 16B load) until both epochs >= need.
// Bounded by watchdog; zeros after abort.
__device__ __forceinline__ float2 poll2(const u64* base, unsigned need, int& dead) {
    if (dead) return make_float2(0.f, 0.f);
    unsigned cnt = 0;
    for (;;) {
        u64 a, b;
        asm volatile("ld.global.cg.v2.u64 {%0,%1}, [%2];"
                     : "=l"(a), "=l"(b) : "l"(base) : "memory");
        if ((unsigned)(a >> 32) >= need && (unsigned)(b >> 32) >= need)
            return make_float2(__uint_as_float((unsigned)a), __uint_as_float((unsigned)b));
        if ((++cnt & 63u) == 0u) {
            if (ld_abort()) { dead = 1; break; }
            if (cnt > POLL_BUDGET) { set_abort(); dead = 1; break; }
        }
        __nanosleep(100);
    }
    return make_float2(0.f, 0.f);
}

// Bounded flag wait for the one-time precompute barrier (64 flags = 16 int4).
__device__ __forceinline__ void flagwait0(int lane) {
    const int4* fp = reinterpret_cast<const int4*>(g_flags0) + (lane & 15);
    unsigned cnt = 0;
    for (;;) {
        int4 v; int ab;
        asm volatile("ld.global.cg.v4.u32 {%0,%1,%2,%3}, [%4];"
                     : "=r"(v.x), "=r"(v.y), "=r"(v.z), "=r"(v.w)
                     : "l"(fp) : "memory");
        asm volatile("ld.global.cg.u32 %0, [%1];"
                     : "=r"(ab) : "l"(&g_abort) : "memory");
        bool done = (v.x >= 1 && v.y >= 1 && v.z >= 1 && v.w >= 1) || (ab != 0);
        if (__all_sync(0xffffffffu, done)) break;
        if (++cnt > POLL_BUDGET) {
            if (lane == 0) set_abort();
            break;
        }
        __nanosleep(150);
    }
    __threadfence();
}

// One warp computes one dot(w_row[1024], h[1024]) from shared memory. (R9 verbatim)
__device__ __forceinline__ float gemv_warp(const float* __restrict__ wrow,
                                           const float* __restrict__ hbuf, int lane) {
    const float4* w4 = reinterpret_cast<const float4*>(wrow);
    const float4* h4 = reinterpret_cast<const float4*>(hbuf);
    float acc = 0.0f;
    #pragma unroll
    for (int i = 0; i < 8; i++) {
        float4 a = w4[i * 32 + lane];
        float4 b = h4[i * 32 + lane];
        acc += a.x * b.x + a.y * b.y + a.z * b.z + a.w * b.w;
    }
    #pragma unroll
    for (int d = 16; d > 0; d >>= 1) acc += __shfl_xor_sync(0xffffffffu, acc, d);
    return acc;
}

__global__ void __launch_bounds__(THREADS, 1)
seqff_kernel(const int* __restrict__ x,
             const float* __restrict__ W0,
             const float* __restrict__ b0,
             const float* __restrict__ Wh,
             const float* __restrict__ bh,
             const float* __restrict__ Wo,
             const float* __restrict__ bo,
             float* __restrict__ out,
             int T)
{
    extern __shared__ float smem[];
    float* Whs   = smem;                       // [3][16][1024] hidden weight rows (192KB)
    float* hbuf  = Whs + 3 * CHUNK * WIDTH;    // 1024: staged input vector
    float* h0s   = hbuf + WIDTH;               // 1024: locally computed h0
    float* ring  = h0s + WIDTH;                // 16: y history window
    float* wos   = ring + 16;                  // 16
    float* out16 = wos + 16;                   // 16: per-layer chunk outputs

    const int tid  = threadIdx.x;
    const int lane = tid & 31;
    const int w    = tid >> 5;
    const int bid  = blockIdx.x;
    const int o0   = bid * CHUNK;

    // ===================== load weights (once) =====================
    // y-window rows of W0 in REGISTERS: this thread's 2 dims (2*tid, 2*tid+1).
    float2 wys[WS];
    #pragma unroll
    for (int k = 0; k < WS; k++)
        wys[k] = *reinterpret_cast<const float2*>(W0 + (size_t)(357 + k) * WIDTH + 2 * tid);

    for (int idx = tid; idx < 3 * CHUNK * WIDTH; idx += THREADS) {
        int layer = idx / (CHUNK * WIDTH), rem = idx % (CHUNK * WIDTH);
        int r = rem >> 10, j = rem & (WIDTH - 1);
        Whs[idx] = Wh[(size_t)layer * WIDTH * WIDTH + (size_t)j * WIDTH + o0 + r];
    }
    if (tid < CHUNK) wos[tid] = Wo[o0 + tid];
    if (tid < 16)    ring[tid] = -10.0f;
    const float bo_reg = __ldg(bo);
    const float bh0 = __ldg(bh + 0 * WIDTH + o0 + (w & 15));
    const float bh1 = __ldg(bh + 1 * WIDTH + o0 + (w & 15));
    const float bh2 = __ldg(bh + 2 * WIDTH + o0 + (w & 15));
    __syncthreads();

    // =============== precompute one-hot part of layer 0 for all t ===============
    for (int t = bid; t < T; t += GRID) {
        float2 acc = *reinterpret_cast<const float2*>(b0 + 2 * tid);
        if (t >= WS) {
            #pragma unroll
            for (int p = 0; p < WS + 1; p++) {
                int r = p * ALPHA + __ldg(x + t - WS + p);
                float2 wv = *reinterpret_cast<const float2*>(W0 + (size_t)r * WIDTH + 2 * tid);
                acc.x += wv.x; acc.y += wv.y;
            }
        } else {
            for (int p = 0; p < WS + 1; p++) {
                int pos = t - WS + p;
                if (pos >= 0) {
                    int r = p * ALPHA + __ldg(x + pos);
                    float2 wv = *reinterpret_cast<const float2*>(W0 + (size_t)r * WIDTH + 2 * tid);
                    acc.x += wv.x; acc.y += wv.y;
                } else {
                    for (int a = 0; a < ALPHA; a++) {
                        int r = p * ALPHA + a;
                        float2 wv = *reinterpret_cast<const float2*>(W0 + (size_t)r * WIDTH + 2 * tid);
                        acc.x += wv.x; acc.y += wv.y;
                    }
                }
            }
        }
        *reinterpret_cast<float2*>(g_hpre + (size_t)t * WIDTH + 2 * tid) = acc;
    }
    __syncthreads();
    if (tid == 0) {
        __threadfence();
        asm volatile("st.global.cg.u32 [%0], %1;" :: "l"(g_flags0 + bid), "r"(1) : "memory");
    }
    if (w == 0) flagwait0(lane);
    __syncthreads();

    // prefetch hpre row 0 (this thread's 2 dims)
    float2 hpre_reg = *reinterpret_cast<const float2*>(g_hpre + 2 * tid);

    int dead = 0;

    // ============================ sequential main loop ============================
    for (int t = 0; t < T; t++) {
        // ---- phase 1: y_{t-1} from 64 partial pairs (every warp, redundantly) ----
        if (t > 0) {
            float2 pv = poll2(g_pp + ((t - 1) & 1) * GRID + 2 * lane, (unsigned)t, dead);
            float s = pv.x + pv.y;
            #pragma unroll
            for (int d = 16; d > 0; d >>= 1) s += __shfl_xor_sync(0xffffffffu, s, d);
            float y = fmaxf(s + bo_reg, 0.0f);
            if (bid == 0 && tid == 0) out[t - 1] = y;
            if (lane == 0) ring[(t + 15) & 15] = y;   // same value from all warps: benign
            __syncwarp();
        }
        // full h0 computed locally by every CTA (wys in registers)
        {
            float2 h = hpre_reg;
            #pragma unroll
            for (int k = 0; k < WS; k++) {
                float yk = ring[(t + k) & 15];
                h.x += yk * wys[k].x; h.y += yk * wys[k].y;
            }
            h.x = fmaxf(h.x, 0.0f); h.y = fmaxf(h.y, 0.0f);
            *reinterpret_cast<float2*>(h0s + 2 * tid) = h;
        }
        __syncthreads();

        // ---- phase 1b: layer-1 GEMV (1 row/warp), coalesced publish h1 pairs ----
        {
            float v = gemv_warp(Whs + (0 * CHUNK + w) * WIDTH, h0s, lane);
            v = fmaxf(v + bh0, 0.0f);
            if (lane == 0) out16[w] = v;
        }
        __syncthreads();
        if (tid < CHUNK)
            st_pair(&g_h1p[o0 + tid], out16[tid], (unsigned)(t + 1));
        // prefetch next step's hpre row (latency hidden across hops 2 and 3)
        if (t + 1 < T)
            hpre_reg = *reinterpret_cast<const float2*>(g_hpre + (size_t)(t + 1) * WIDTH + 2 * tid);

        // ---- phase 2: poll h1 pairs (this thread's 2 dims), stage, GEMV, publish h2 ----
        {
            float2 hv = poll2(g_h1p + 2 * tid, (unsigned)(t + 1), dead);
            *reinterpret_cast<float2*>(hbuf + 2 * tid) = hv;
        }
        __syncthreads();
        {
            float v = gemv_warp(Whs + (1 * CHUNK + w) * WIDTH, hbuf, lane);
            v = fmaxf(v + bh1, 0.0f);
            if (lane == 0) out16[w] = v;
        }
        __syncthreads();
        if (tid < CHUNK)
            st_pair(&g_h2p[o0 + tid], out16[tid], (unsigned)(t + 1));

        // ---- phase 3: poll h2 pairs, stage, GEMV, fold output dot, publish partial ----
        {
            float2 hv = poll2(g_h2p + 2 * tid, (unsigned)(t + 1), dead);
            *reinterpret_cast<float2*>(hbuf + 2 * tid) = hv;
        }
        __syncthreads();
        {
            float v = gemv_warp(Whs + (2 * CHUNK + w) * WIDTH, hbuf, lane);
            v = fmaxf(v + bh2, 0.0f);
            if (lane == 0) out16[w] = v;
        }
        __syncthreads();
        if (tid == 0) {
            float p = 0.0f;
            #pragma unroll
            for (int i = 0; i < CHUNK; i++) p += out16[i] * wos[i];
            st_pair(&g_pp[(t & 1) * GRID + bid], p, (unsigned)(t + 1));
        }
    }

    // ---------------- epilogue: final output y[T-1] ----------------
    if (bid == 0 && w == 0) {
        float2 pv = poll2(g_pp + ((T - 1) & 1) * GRID + 2 * lane, (unsigned)T, dead);
        float s = pv.x + pv.y;
        #pragma unroll
        for (int d = 16; d > 0; d >>= 1) s += __shfl_xor_sync(0xffffffffu, s, d);
        if (lane == 0) out[T - 1] = fmaxf(s + bo_reg, 0.0f);
    }
}

extern "C" void kernel_launch(void* const* d_in, const int* in_sizes, int n_in,
                              void* d_out, int out_size)
{
    const int*   x  = (const int*)  d_in[0];
    const float* W0 = (const float*)d_in[1];
    const float* b0 = (const float*)d_in[2];
    const float* Wh = (const float*)d_in[3];
    const float* bh = (const float*)d_in[4];
    const float* Wo = (const float*)d_in[5];
    const float* bo = (const float*)d_in[6];
    float* out = (float*)d_out;
    int T = in_sizes[0];
    if (T > T_MAX) T = T_MAX;

    const int smem_bytes = (3 * CHUNK * WIDTH + WIDTH + WIDTH + 16 + 16 + 16) * 4; // ~205KB
    cudaFuncSetAttribute(seqff_kernel, cudaFuncAttributeMaxDynamicSharedMemorySize, smem_bytes);

    init_kernel<<<4, 512>>>();
    seqff_kernel<<<GRID, THREADS, smem_bytes>>>(x, W0, b0, Wh, bh, Wo, bo, out, T);
}

// round 12
// speedup vs baseline: 2.5490x; 1.2904x over previous
#include <cuda_runtime.h>
#include <cuda_bf16.h>

#define T_MAX   16384
#define WIDTH   1024
#define GRIDP   32          // CTAs per layer group
#define NGROUP  3
#define GRID    (GRIDP * NGROUP)   // 96
#define THREADS 512
#define NW      16
#define CHUNK   32          // output dims per CTA (1024/32)
#define WS      16
#define ALPHA   21
#define POLL_BUDGET (1u << 17)

typedef unsigned long long u64;

// ---- global scratch (static __device__ arrays: allocation-free) ----
// Pair format: high 32 bits = epoch, low 32 bits = f32 value bits.
__device__ __align__(16) int g_flags0[GRID];        // precompute barrier
__device__ int g_abort;
__device__ __align__(16) u64 g_h1p[WIDTH];          // h1 pairs (written by group 0)
__device__ __align__(16) u64 g_h2p[WIDTH];          // h2 pairs (written by group 1)
__device__ __align__(16) u64 g_pp[2 * GRIDP];       // partial pairs, parity-slotted (group 2)
__device__ float g_hpre[(size_t)T_MAX * WIDTH];     // one-hot part of layer0, per timestep

__global__ void init_kernel() {
    int i = blockIdx.x * blockDim.x + threadIdx.x;
    if (i < WIDTH)     { g_h1p[i] = 0ull; g_h2p[i] = 0ull; }
    if (i < 2 * GRIDP) g_pp[i] = 0ull;
    if (i < GRID)      g_flags0[i] = 0;
    if (i == 0)        g_abort = 0;
}

// ------------------------------- helpers ----------------------------------
__device__ __forceinline__ void st_pair(u64* p, float v, unsigned e) {
    u64 x = ((u64)e << 32) | (u64)__float_as_uint(v);
    asm volatile("st.relaxed.gpu.global.u64 [%0], %1;" :: "l"(p), "l"(x) : "memory");
}
__device__ __forceinline__ int ld_abort() {
    int a;
    asm volatile("ld.global.cg.u32 %0, [%1];" : "=r"(a) : "l"(&g_abort) : "memory");
    return a;
}
__device__ __forceinline__ void set_abort() {
    asm volatile("st.global.cg.u32 [%0], %1;" :: "l"(&g_abort), "r"(1) : "memory");
}

// Per-thread: poll 2 consecutive pairs (one 16B load) until both epochs >= need.
// Bounded by watchdog; zeros after abort. (R11 verbatim)
__device__ __forceinline__ float2 poll2(const u64* base, unsigned need, int& dead) {
    if (dead) return make_float2(0.f, 0.f);
    unsigned cnt = 0;
    for (;;) {
        u64 a, b;
        asm volatile("ld.global.cg.v2.u64 {%0,%1}, [%2];"
                     : "=l"(a), "=l"(b) : "l"(base) : "memory");
        if ((unsigned)(a >> 32) >= need && (unsigned)(b >> 32) >= need)
            return make_float2(__uint_as_float((unsigned)a), __uint_as_float((unsigned)b));
        if ((++cnt & 63u) == 0u) {
            if (ld_abort()) { dead = 1; break; }
            if (cnt > POLL_BUDGET) { set_abort(); dead = 1; break; }
        }
        __nanosleep(100);
    }
    return make_float2(0.f, 0.f);
}

// Bounded flag wait for the one-time precompute barrier (96 flags = 24 int4).
__device__ __forceinline__ void flagwait0(int lane) {
    int idx = (lane < 24) ? lane : (lane - 24);
    const int4* fp = reinterpret_cast<const int4*>(g_flags0) + idx;
    unsigned cnt = 0;
    for (;;) {
        int4 v; int ab;
        asm volatile("ld.global.cg.v4.u32 {%0,%1,%2,%3}, [%4];"
                     : "=r"(v.x), "=r"(v.y), "=r"(v.z), "=r"(v.w)
                     : "l"(fp) : "memory");
        asm volatile("ld.global.cg.u32 %0, [%1];"
                     : "=r"(ab) : "l"(&g_abort) : "memory");
        bool done = (v.x >= 1 && v.y >= 1 && v.z >= 1 && v.w >= 1) || (ab != 0);
        if (__all_sync(0xffffffffu, done)) break;
        if (++cnt > POLL_BUDGET) {
            if (lane == 0) set_abort();
            break;
        }
        __nanosleep(150);
    }
    __threadfence();
}

// One warp computes one dot(w_row[1024], h[1024]) from shared memory. (R11 verbatim)
__device__ __forceinline__ float gemv_warp(const float* __restrict__ wrow,
                                           const float* __restrict__ hbuf, int lane) {
    const float4* w4 = reinterpret_cast<const float4*>(wrow);
    const float4* h4 = reinterpret_cast<const float4*>(hbuf);
    float acc = 0.0f;
    #pragma unroll
    for (int i = 0; i < 8; i++) {
        float4 a = w4[i * 32 + lane];
        float4 b = h4[i * 32 + lane];
        acc += a.x * b.x + a.y * b.y + a.z * b.z + a.w * b.w;
    }
    #pragma unroll
    for (int d = 16; d > 0; d >>= 1) acc += __shfl_xor_sync(0xffffffffu, acc, d);
    return acc;
}

__global__ void __launch_bounds__(THREADS, 1)
seqff_kernel(const int* __restrict__ x,
             const float* __restrict__ W0,
             const float* __restrict__ b0,
             const float* __restrict__ Wh,
             const float* __restrict__ bh,
             const float* __restrict__ Wo,
             const float* __restrict__ bo,
             float* __restrict__ out,
             int T)
{
    extern __shared__ float smem[];
    float* Whs   = smem;                       // [32][1024] ONE layer's rows (128KB)
    float* hbuf  = Whs + CHUNK * WIDTH;        // 1024: staged input vector / h0
    float* ring  = hbuf + WIDTH;               // 16: y history window (group 0 only)
    float* wos   = ring + 16;                  // 32 (group 2 only)
    float* out32 = wos + 32;                   // 32: per-layer chunk outputs

    const int tid   = threadIdx.x;
    const int lane  = tid & 31;
    const int w     = tid >> 5;
    const int bid   = blockIdx.x;
    const int group = bid / GRIDP;             // 0: h0+L1, 1: L2, 2: L3+partial
    const int gid   = bid - group * GRIDP;
    const int o0    = gid * CHUNK;

    // ===================== load weights (once) =====================
    // y-window rows of W0 in REGISTERS (used by group 0 only): dims 2*tid, 2*tid+1.
    float2 wys[WS];
    #pragma unroll
    for (int k = 0; k < WS; k++)
        wys[k] = *reinterpret_cast<const float2*>(W0 + (size_t)(357 + k) * WIDTH + 2 * tid);

    // this CTA's single layer slice: rows o0..o0+31 of layer `group`
    for (int idx = tid; idx < CHUNK * WIDTH; idx += THREADS) {
        int r = idx >> 10, j = idx & (WIDTH - 1);
        Whs[idx] = Wh[(size_t)group * WIDTH * WIDTH + (size_t)j * WIDTH + o0 + r];
    }
    if (tid < CHUNK) wos[tid] = Wo[o0 + tid];
    if (tid < 16)    ring[tid] = -10.0f;
    const float bo_reg = __ldg(bo);
    const float bhA = __ldg(bh + (size_t)group * WIDTH + o0 + w);
    const float bhB = __ldg(bh + (size_t)group * WIDTH + o0 + w + 16);
    __syncthreads();

    // =============== precompute one-hot part of layer 0 for all t ===============
    for (int t = bid; t < T; t += GRID) {
        float2 acc = *reinterpret_cast<const float2*>(b0 + 2 * tid);
        if (t >= WS) {
            #pragma unroll
            for (int p = 0; p < WS + 1; p++) {
                int r = p * ALPHA + __ldg(x + t - WS + p);
                float2 wv = *reinterpret_cast<const float2*>(W0 + (size_t)r * WIDTH + 2 * tid);
                acc.x += wv.x; acc.y += wv.y;
            }
        } else {
            for (int p = 0; p < WS + 1; p++) {
                int pos = t - WS + p;
                if (pos >= 0) {
                    int r = p * ALPHA + __ldg(x + pos);
                    float2 wv = *reinterpret_cast<const float2*>(W0 + (size_t)r * WIDTH + 2 * tid);
                    acc.x += wv.x; acc.y += wv.y;
                } else {
                    for (int a = 0; a < ALPHA; a++) {
                        int r = p * ALPHA + a;
                        float2 wv = *reinterpret_cast<const float2*>(W0 + (size_t)r * WIDTH + 2 * tid);
                        acc.x += wv.x; acc.y += wv.y;
                    }
                }
            }
        }
        *reinterpret_cast<float2*>(g_hpre + (size_t)t * WIDTH + 2 * tid) = acc;
    }
    __syncthreads();
    if (tid == 0) {
        __threadfence();
        asm volatile("st.global.cg.u32 [%0], %1;" :: "l"(g_flags0 + bid), "r"(1) : "memory");
    }
    if (w == 0) flagwait0(lane);
    __syncthreads();

    float2 hpre_reg = make_float2(0.f, 0.f);
    if (group == 0)
        hpre_reg = *reinterpret_cast<const float2*>(g_hpre + 2 * tid);

    int dead = 0;

    // ============================ sequential main loop ============================
    for (int t = 0; t < T; t++) {
        if (group == 0) {
            // ---- y_{t-1} from 32 partial pairs (every warp, redundantly) ----
            if (t > 0) {
                float2 pv = poll2(g_pp + ((t - 1) & 1) * GRIDP + 2 * (lane & 15), (unsigned)t, dead);
                float s = (lane < 16) ? (pv.x + pv.y) : 0.0f;
                #pragma unroll
                for (int d = 16; d > 0; d >>= 1) s += __shfl_xor_sync(0xffffffffu, s, d);
                float y = fmaxf(s + bo_reg, 0.0f);
                if (bid == 0 && tid == 0) out[t - 1] = y;
                if (lane == 0) ring[(t + 15) & 15] = y;
                __syncwarp();
            }
            // full h0 locally (wys in registers, hpre prefetched)
            {
                float2 h = hpre_reg;
                #pragma unroll
                for (int k = 0; k < WS; k++) {
                    float yk = ring[(t + k) & 15];
                    h.x += yk * wys[k].x; h.y += yk * wys[k].y;
                }
                h.x = fmaxf(h.x, 0.0f); h.y = fmaxf(h.y, 0.0f);
                *reinterpret_cast<float2*>(hbuf + 2 * tid) = h;
            }
            __syncthreads();
            // layer-1 GEMV (2 rows/warp), coalesced publish h1 pairs
            {
                float v0 = gemv_warp(Whs + w * WIDTH, hbuf, lane);
                float v1 = gemv_warp(Whs + (w + 16) * WIDTH, hbuf, lane);
                if (lane == 0) {
                    out32[w]      = fmaxf(v0 + bhA, 0.0f);
                    out32[w + 16] = fmaxf(v1 + bhB, 0.0f);
                }
            }
            __syncthreads();
            if (tid < CHUNK)
                st_pair(&g_h1p[o0 + tid], out32[tid], (unsigned)(t + 1));
            // prefetch next step's hpre row
            if (t + 1 < T)
                hpre_reg = *reinterpret_cast<const float2*>(g_hpre + (size_t)(t + 1) * WIDTH + 2 * tid);
        } else if (group == 1) {
            // ---- poll full h1 (this thread's 2 dims), GEMV layer 2, publish h2 ----
            {
                float2 hv = poll2(g_h1p + 2 * tid, (unsigned)(t + 1), dead);
                *reinterpret_cast<float2*>(hbuf + 2 * tid) = hv;
            }
            __syncthreads();
            {
                float v0 = gemv_warp(Whs + w * WIDTH, hbuf, lane);
                float v1 = gemv_warp(Whs + (w + 16) * WIDTH, hbuf, lane);
                if (lane == 0) {
                    out32[w]      = fmaxf(v0 + bhA, 0.0f);
                    out32[w + 16] = fmaxf(v1 + bhB, 0.0f);
                }
            }
            __syncthreads();
            if (tid < CHUNK)
                st_pair(&g_h2p[o0 + tid], out32[tid], (unsigned)(t + 1));
            __syncthreads();   // protect hbuf WAR across iterations
        } else {
            // ---- poll full h2, GEMV layer 3, fold Wo dot, publish partial ----
            {
                float2 hv = poll2(g_h2p + 2 * tid, (unsigned)(t + 1), dead);
                *reinterpret_cast<float2*>(hbuf + 2 * tid) = hv;
            }
            __syncthreads();
            {
                float v0 = gemv_warp(Whs + w * WIDTH, hbuf, lane);
                float v1 = gemv_warp(Whs + (w + 16) * WIDTH, hbuf, lane);
                if (lane == 0) {
                    out32[w]      = fmaxf(v0 + bhA, 0.0f);
                    out32[w + 16] = fmaxf(v1 + bhB, 0.0f);
                }
            }
            __syncthreads();
            if (tid == 0) {
                float p = 0.0f;
                #pragma unroll
                for (int i = 0; i < CHUNK; i++) p += out32[i] * wos[i];
                st_pair(&g_pp[(t & 1) * GRIDP + gid], p, (unsigned)(t + 1));
            }
            __syncthreads();   // protect hbuf WAR across iterations
        }
    }

    // ---------------- epilogue: final output y[T-1] ----------------
    if (bid == 0 && w == 0) {
        float2 pv = poll2(g_pp + ((T - 1) & 1) * GRIDP + 2 * (lane & 15), (unsigned)T, dead);
        float s = (lane < 16) ? (pv.x + pv.y) : 0.0f;
        #pragma unroll
        for (int d = 16; d > 0; d >>= 1) s += __shfl_xor_sync(0xffffffffu, s, d);
        if (lane == 0) out[T - 1] = fmaxf(s + bo_reg, 0.0f);
    }
}

extern "C" void kernel_launch(void* const* d_in, const int* in_sizes, int n_in,
                              void* d_out, int out_size)
{
    const int*   x  = (const int*)  d_in[0];
    const float* W0 = (const float*)d_in[1];
    const float* b0 = (const float*)d_in[2];
    const float* Wh = (const float*)d_in[3];
    const float* bh = (const float*)d_in[4];
    const float* Wo = (const float*)d_in[5];
    const float* bo = (const float*)d_in[6];
    float* out = (float*)d_out;
    int T = in_sizes[0];
    if (T > T_MAX) T = T_MAX;

    const int smem_bytes = (CHUNK * WIDTH + WIDTH + 16 + 32 + 32) * 4;  // ~136KB
    cudaFuncSetAttribute(seqff_kernel, cudaFuncAttributeMaxDynamicSharedMemorySize, smem_bytes);

    init_kernel<<<4, 512>>>();
    seqff_kernel<<<GRID, THREADS, smem_bytes>>>(x, W0, b0, Wh, bh, Wo, bo, out, T);
}